// round 9
// baseline (speedup 1.0000x reference)
#include <cuda_runtime.h>
#include <cstdint>

#define ZCH_CAP 400000
#define NBUCKETS 16384
#define MAX_BLOCKS 8192          // search grid: ceil(2e6/256) = 7813 <= 8192
#define IHS 4000000ULL           // INPUT_HASH_SIZE

// Scratch (no cudaMalloc allowed). Flat arrays, feature-offset indexed.
__device__ int   g_is64;
__device__ float g_rowsum[2 * ZCH_CAP];
__device__ int   g_bstart[2 * (NBUCKETS + 1)];
__device__ float g_partial[MAX_BLOCKS];

// ---------------------------------------------------------------------------
// Dtype probe: mch values are < 2^22, so if stored as int64 every odd int32
// word is zero. Reads only 256B (in-bounds for both interpretations).
__global__ void detect_kernel(const void* mch0) {
    if (threadIdx.x == 0) {
        const int* w = (const int*)mch0;
        int nz = 0;
        for (int k = 1; k < 64; k += 2) nz += (w[k] != 0) ? 1 : 0;
        g_is64 = (nz == 0) ? 1 : 0;
    }
}

// ---------------------------------------------------------------------------
// lower_bound (== jnp.searchsorted side='left') over a sorted range of T.
template <typename T>
__device__ __forceinline__ int lower_bound_range(const T* t, int lo, int n,
                                                 long long key) {
    while (n > 0) {
        int half = n >> 1;
        long long v = (long long)t[lo + half];
        if (v < key) { lo += half + 1; n -= half + 1; }
        else         { n = half; }
    }
    return lo;
}

// ---------------------------------------------------------------------------
// Bucket index: g_bstart[f*(NB+1)+b] = lower_bound(mch_f, ceil(b*IHS/NB)).
template <typename T>
__device__ __forceinline__ void bucket_body(const void* mch0v, const void* mch1v,
                                            int zch, int t) {
    int f = (t > NBUCKETS) ? 1 : 0;
    int b = t - f * (NBUCKETS + 1);
    const T* mch = (const T*)((f == 0) ? mch0v : mch1v);
    long long thr = (long long)(((unsigned long long)b * IHS + NBUCKETS - 1)
                                / NBUCKETS);
    g_bstart[t] = lower_bound_range<T>(mch, 0, zch, thr);
}

__global__ void bucket_kernel(const void* mch0, const void* mch1, int zch) {
    int t = blockIdx.x * blockDim.x + threadIdx.x;
    if (t >= 2 * (NBUCKETS + 1)) return;
    if (g_is64) bucket_body<long long>(mch0, mch1, zch, t);  // uniform branch
    else        bucket_body<int>(mch0, mch1, zch, t);
}

// ---------------------------------------------------------------------------
// Kernel A: one 128-thread block per embedding row; coalesced 512B load,
// shared tree reduce, thread 0 writes the row sum. (float32 either way.)
__global__ void rowsum_kernel(const float* emb0, const float* emb1, int zch) {
    __shared__ float sh[128];
    const int slot = blockIdx.x;                  // 0 .. 2*zch-1
    const int f    = (slot >= zch) ? 1 : 0;
    const int row  = slot - f * zch;
    const float* emb = (f == 0) ? emb0 : emb1;

    sh[threadIdx.x] = emb[(size_t)row * blockDim.x + threadIdx.x];
    __syncthreads();
    for (int o = blockDim.x >> 1; o > 0; o >>= 1) {
        if (threadIdx.x < (unsigned)o) sh[threadIdx.x] += sh[threadIdx.x + o];
        __syncthreads();
    }
    if (threadIdx.x == 0) g_rowsum[f * ZCH_CAP + row] = sh[0];
}

// ---------------------------------------------------------------------------
// Kernel B body: bucketized lower_bound -> remapped index (float to d_out),
// gather the 4B rowsum (L2-resident); returns it for the block reduction.
template <typename T>
__device__ __forceinline__ float search_body(const void* ids0v, const void* ids1v,
                                             const void* mch0v, const void* mch1v,
                                             float* out, int n, int zch,
                                             int out_size, int tid) {
    const int f = (tid >= n) ? 1 : 0;
    const int i = tid - f * n;
    const T* ids = (const T*)((f == 0) ? ids0v : ids1v);
    const T* mch = (const T*)((f == 0) ? mch0v : mch1v);

    const long long id = (long long)ids[i];
    int b = (int)((unsigned long long)id * NBUCKETS / IHS);
    if (b < 0) b = 0;
    if (b > NBUCKETS - 1) b = NBUCKETS - 1;
    const int bi  = f * (NBUCKETS + 1) + b;
    const int lo0 = g_bstart[bi];
    const int hi0 = g_bstart[bi + 1];

    int pos = lower_bound_range<T>(mch, lo0, hi0 - lo0, id);
    if (pos > zch - 1) pos = zch - 1;
    const int r = ((long long)mch[pos] == id) ? pos : (zch - 1);

    if (1 + tid < out_size)
        out[1 + tid] = (float)r;          // remapped_0 then remapped_1
    return g_rowsum[f * ZCH_CAP + r];
}

__global__ void search_kernel(const void* ids0, const void* ids1,
                              const void* mch0, const void* mch1,
                              float* out, int n, int zch, int out_size) {
    __shared__ float sh[256];
    const int tid = blockIdx.x * blockDim.x + threadIdx.x;

    float s = 0.0f;
    if (tid < 2 * n) {
        if (g_is64)                       // uniform branch: only one width of
            s = search_body<long long>(ids0, ids1, mch0, mch1,   // load ever
                                       out, n, zch, out_size, tid); // issues
        else
            s = search_body<int>(ids0, ids1, mch0, mch1,
                                 out, n, zch, out_size, tid);
    }

    sh[threadIdx.x] = s;
    __syncthreads();
    for (int o = 128; o > 0; o >>= 1) {
        if (threadIdx.x < (unsigned)o) sh[threadIdx.x] += sh[threadIdx.x + o];
        __syncthreads();
    }
    if (threadIdx.x == 0) g_partial[blockIdx.x] = sh[0];
}

// ---------------------------------------------------------------------------
// Final reduce: one block, fixed-order double accumulation (deterministic),
// loss = mean over [2N, emb_dim].
__global__ void finalize_kernel(float* out, int nblocks, int n, int emb_dim) {
    __shared__ double red[256];
    double acc = 0.0;
    for (int i = threadIdx.x; i < nblocks; i += 256)
        acc += (double)g_partial[i];
    red[threadIdx.x] = acc;
    __syncthreads();
    for (int o = 128; o > 0; o >>= 1) {
        if (threadIdx.x < (unsigned)o) red[threadIdx.x] += red[threadIdx.x + o];
        __syncthreads();
    }
    if (threadIdx.x == 0)
        out[0] = (float)(red[0] / ((double)(2 * n) * (double)emb_dim));
}

// ---------------------------------------------------------------------------
extern "C" void kernel_launch(void* const* d_in, const int* in_sizes, int n_in,
                              void* d_out, int out_size) {
    // Identify inputs by element count (robust to metadata ordering):
    //   ~51.2M -> emb, ~1M -> ids, ~400K -> mch. First hit = feature 0.
    const void* idsp[2] = {0, 0};
    const void* mchp[2] = {0, 0};
    const void* embp[2] = {0, 0};
    int n_ids = 0, n_mch = 0, n_emb = 0;
    int sz_ids = 0, sz_mch = 0, sz_emb = 0;
    for (int i = 0; i < n_in; i++) {
        int s = in_sizes[i];
        if (s > 10000000)      { if (n_emb < 2) { embp[n_emb++] = d_in[i]; sz_emb = s; } }
        else if (s > 600000)   { if (n_ids < 2) { idsp[n_ids++] = d_in[i]; sz_ids = s; } }
        else                   { if (n_mch < 2) { mchp[n_mch++] = d_in[i]; sz_mch = s; } }
    }
    float* out = (float*)d_out;

    const int n       = sz_ids;                    // ids per feature (1e6)
    int       zch     = sz_mch;                    // 400000
    if (zch > ZCH_CAP) zch = ZCH_CAP;
    const int emb_dim = (zch > 0) ? (sz_emb / zch) : 128;   // 128

    detect_kernel<<<1, 32>>>(mchp[0]);

    {   // Bucket index.
        const int total = 2 * (NBUCKETS + 1);
        bucket_kernel<<<(total + 255) / 256, 256>>>(mchp[0], mchp[1], zch);
    }

    // Kernel A: one block per row, both features (emb_dim = 128 threads).
    rowsum_kernel<<<2 * zch, emb_dim>>>((const float*)embp[0],
                                        (const float*)embp[1], zch);

    // Kernel B: one thread per id across both features.
    const int nblocks = (2 * n + 255) / 256;
    search_kernel<<<nblocks, 256>>>(idsp[0], idsp[1], mchp[0], mchp[1],
                                    out, n, zch, out_size);

    finalize_kernel<<<1, 256>>>(out, nblocks, n, emb_dim);
}

// round 11
// speedup vs baseline: 4.7917x; 4.7917x over previous
#include <cuda_runtime.h>
#include <cstdint>

#define ZCH_CAP 400000
#define NBUCKETS 16384
#define MAX_BLOCKS 8192          // search grid: ceil(2e6/256) = 7813 <= 8192
#define IHS 4000000ULL           // INPUT_HASH_SIZE

// Scratch (no cudaMalloc allowed). Flat arrays, feature-offset indexed.
__device__ int   g_is64;
__device__ float g_rowsum[2 * ZCH_CAP];
__device__ int   g_bstart[2 * (NBUCKETS + 1)];
__device__ float g_partial[MAX_BLOCKS];

// ---------------------------------------------------------------------------
// Dtype probe: mch values are < 2^22, so if stored as int64 every odd int32
// word is zero. Reads only 256B (in-bounds for both interpretations).
__global__ void detect_kernel(const void* mch0) {
    if (threadIdx.x == 0) {
        const int* w = (const int*)mch0;
        int nz = 0;
        for (int k = 1; k < 64; k += 2) nz += (w[k] != 0) ? 1 : 0;
        g_is64 = (nz == 0) ? 1 : 0;
    }
}

// ---------------------------------------------------------------------------
// lower_bound (== jnp.searchsorted side='left') over a sorted range of T.
template <typename T>
__device__ __forceinline__ int lower_bound_range(const T* __restrict__ t,
                                                 int lo, int n, long long key) {
    #pragma unroll 1
    while (n > 0) {
        int half = n >> 1;
        long long v = (long long)t[lo + half];
        if (v < key) { lo += half + 1; n -= half + 1; }
        else         { n = half; }
    }
    return lo;
}

// ---------------------------------------------------------------------------
// Bucket index: g_bstart[f*(NB+1)+b] = lower_bound(mch_f, ceil(b*IHS/NB)).
template <typename T>
__device__ __forceinline__ void bucket_body(const void* mch0v, const void* mch1v,
                                            int zch, int t) {
    int f = (t > NBUCKETS) ? 1 : 0;
    int b = t - f * (NBUCKETS + 1);
    const T* mch = (const T*)((f == 0) ? mch0v : mch1v);
    long long thr = (long long)(((unsigned long long)b * IHS + NBUCKETS - 1)
                                / NBUCKETS);
    g_bstart[t] = lower_bound_range<T>(mch, 0, zch, thr);
}

__global__ void bucket_kernel(const void* mch0, const void* mch1, int zch) {
    int t = blockIdx.x * blockDim.x + threadIdx.x;
    if (t >= 2 * (NBUCKETS + 1)) return;
    if (g_is64) bucket_body<long long>(mch0, mch1, zch, t);  // uniform branch
    else        bucket_body<int>(mch0, mch1, zch, t);
}

// ---------------------------------------------------------------------------
// Kernel A: one WARP per embedding row (emb_dim=128). Lane loads one float4
// (512B/warp fully coalesced), warp-shuffle reduce, lane 0 writes the sum.
// 8 warps/block -> 8 independent 16B loads in flight per scheduler.
__global__ void rowsum_kernel(const float* __restrict__ emb0,
                              const float* __restrict__ emb1, int zch) {
    const int warp = (blockIdx.x * blockDim.x + threadIdx.x) >> 5;
    const int lane = threadIdx.x & 31;
    if (warp >= 2 * zch) return;

    const int f   = (warp >= zch) ? 1 : 0;
    const int row = warp - f * zch;
    const float* __restrict__ emb = (f == 0) ? emb0 : emb1;

    const float4 v = reinterpret_cast<const float4*>(
        emb + (size_t)row * 128)[lane];
    float s = (v.x + v.y) + (v.z + v.w);
    #pragma unroll
    for (int o = 16; o > 0; o >>= 1)
        s += __shfl_down_sync(0xffffffffu, s, o);
    if (lane == 0) g_rowsum[f * ZCH_CAP + row] = s;
}

// ---------------------------------------------------------------------------
// Kernel B body: bucketized lower_bound -> remapped index (float to d_out),
// gather the 4B rowsum (L2-resident); returns it for the block reduction.
template <typename T>
__device__ __forceinline__ float search_body(const void* ids0v, const void* ids1v,
                                             const void* mch0v, const void* mch1v,
                                             float* __restrict__ out,
                                             int n, int zch, int out_size,
                                             int tid) {
    const int f = (tid >= n) ? 1 : 0;
    const int i = tid - f * n;
    const T* __restrict__ ids = (const T*)((f == 0) ? ids0v : ids1v);
    const T* __restrict__ mch = (const T*)((f == 0) ? mch0v : mch1v);

    const long long id = (long long)ids[i];
    int b = (int)((unsigned long long)id * NBUCKETS / IHS);
    if (b < 0) b = 0;
    if (b > NBUCKETS - 1) b = NBUCKETS - 1;
    const int bi  = f * (NBUCKETS + 1) + b;
    const int lo0 = __ldg(&g_bstart[bi]);
    const int hi0 = __ldg(&g_bstart[bi + 1]);

    int pos = lower_bound_range<T>(mch, lo0, hi0 - lo0, id);
    if (pos > zch - 1) pos = zch - 1;
    const int r = ((long long)mch[pos] == id) ? pos : (zch - 1);

    if (1 + tid < out_size)
        out[1 + tid] = (float)r;          // remapped_0 then remapped_1
    return __ldg(&g_rowsum[f * ZCH_CAP + r]);
}

__global__ void search_kernel(const void* ids0, const void* ids1,
                              const void* mch0, const void* mch1,
                              float* __restrict__ out,
                              int n, int zch, int out_size) {
    const int tid = blockIdx.x * blockDim.x + threadIdx.x;

    float s = 0.0f;
    if (tid < 2 * n) {
        if (g_is64)                       // uniform branch: only one width of
            s = search_body<long long>(ids0, ids1, mch0, mch1,   // load ever
                                       out, n, zch, out_size, tid); // issues
        else
            s = search_body<int>(ids0, ids1, mch0, mch1,
                                 out, n, zch, out_size, tid);
    }

    // Warp shuffle reduce, then one cross-warp pass (single __syncthreads).
    #pragma unroll
    for (int o = 16; o > 0; o >>= 1)
        s += __shfl_down_sync(0xffffffffu, s, o);

    __shared__ float warp_sums[8];        // blockDim = 256 -> 8 warps
    const int lane = threadIdx.x & 31;
    const int wid  = threadIdx.x >> 5;
    if (lane == 0) warp_sums[wid] = s;
    __syncthreads();
    if (wid == 0) {
        float b2 = (lane < 8) ? warp_sums[lane] : 0.0f;
        #pragma unroll
        for (int o = 4; o > 0; o >>= 1)
            b2 += __shfl_down_sync(0xffffffffu, b2, o);
        if (lane == 0) g_partial[blockIdx.x] = b2;
    }
}

// ---------------------------------------------------------------------------
// Final reduce: one block, fixed-order double accumulation (deterministic),
// loss = mean over [2N, emb_dim].
__global__ void finalize_kernel(float* __restrict__ out, int nblocks, int n,
                                int emb_dim) {
    __shared__ double red[256];
    double acc = 0.0;
    for (int i = threadIdx.x; i < nblocks; i += 256)
        acc += (double)g_partial[i];
    red[threadIdx.x] = acc;
    __syncthreads();
    for (int o = 128; o > 0; o >>= 1) {
        if (threadIdx.x < (unsigned)o) red[threadIdx.x] += red[threadIdx.x + o];
        __syncthreads();
    }
    if (threadIdx.x == 0)
        out[0] = (float)(red[0] / ((double)(2 * n) * (double)emb_dim));
}

// ---------------------------------------------------------------------------
extern "C" void kernel_launch(void* const* d_in, const int* in_sizes, int n_in,
                              void* d_out, int out_size) {
    // Identify inputs by element count (robust to metadata ordering):
    //   ~51.2M -> emb, ~1M -> ids, ~400K -> mch. First hit = feature 0.
    const void* idsp[2] = {0, 0};
    const void* mchp[2] = {0, 0};
    const void* embp[2] = {0, 0};
    int n_ids = 0, n_mch = 0, n_emb = 0;
    int sz_ids = 0, sz_mch = 0, sz_emb = 0;
    for (int i = 0; i < n_in; i++) {
        int s = in_sizes[i];
        if (s > 10000000)      { if (n_emb < 2) { embp[n_emb++] = d_in[i]; sz_emb = s; } }
        else if (s > 600000)   { if (n_ids < 2) { idsp[n_ids++] = d_in[i]; sz_ids = s; } }
        else                   { if (n_mch < 2) { mchp[n_mch++] = d_in[i]; sz_mch = s; } }
    }
    float* out = (float*)d_out;

    const int n       = sz_ids;                    // ids per feature (1e6)
    int       zch     = sz_mch;                    // 400000
    if (zch > ZCH_CAP) zch = ZCH_CAP;
    const int emb_dim = (zch > 0) ? (sz_emb / zch) : 128;   // 128

    detect_kernel<<<1, 32>>>(mchp[0]);

    {   // Bucket index.
        const int total = 2 * (NBUCKETS + 1);
        bucket_kernel<<<(total + 255) / 256, 256>>>(mchp[0], mchp[1], zch);
    }

    // Kernel A: warp per row, 8 warps per 256-thread block.
    {
        const int warps = 2 * zch;
        rowsum_kernel<<<(warps + 7) / 8, 256>>>((const float*)embp[0],
                                                (const float*)embp[1], zch);
    }

    // Kernel B: one thread per id across both features.
    const int nblocks = (2 * n + 255) / 256;
    search_kernel<<<nblocks, 256>>>(idsp[0], idsp[1], mchp[0], mchp[1],
                                    out, n, zch, out_size);

    finalize_kernel<<<1, 256>>>(out, nblocks, n, emb_dim);
}

// round 13
// speedup vs baseline: 5.7010x; 1.1898x over previous
#include <cuda_runtime.h>
#include <cstdint>

#define ZCH_CAP 400000
#define NBUCKETS 65536
#define MAX_BLOCKS 8192          // search grid: ceil(2e6/512) = 3907 <= 8192
#define IHS 4000000ULL           // INPUT_HASH_SIZE

// Scratch (no cudaMalloc allowed). Flat arrays, feature-offset indexed.
__device__ float g_rowsum[2 * ZCH_CAP];
__device__ int   g_bstart[2 * (NBUCKETS + 1)];
__device__ float g_partial[MAX_BLOCKS];
__device__ int   g_ticket;       // zero-init; reset by finalizing block

// ---------------------------------------------------------------------------
// Inline dtype probe: mch values < 2^22, so int64 storage => odd int32 words
// of the first entries are all zero. int32 storage => they are real sorted
// values; all-8-zero requires >=8 duplicate zeros in the table (P ~ 1e-12).
// Uniform across threads; L1-broadcast loads.
__device__ __forceinline__ int detect_is64(const void* mch0) {
    const int* w = (const int*)mch0;
    int acc = 0;
    #pragma unroll
    for (int k = 1; k < 16; k += 2) acc |= w[k];
    return acc == 0;
}

// ---------------------------------------------------------------------------
// lower_bound (== jnp.searchsorted side='left') over a sorted range of T.
template <typename T>
__device__ __forceinline__ int lower_bound_range(const T* __restrict__ t,
                                                 int lo, int n, long long key) {
    #pragma unroll 1
    while (n > 0) {
        int half = n >> 1;
        long long v = (long long)t[lo + half];
        if (v < key) { lo += half + 1; n -= half + 1; }
        else         { n = half; }
    }
    return lo;
}

// ---------------------------------------------------------------------------
// Bucket index: g_bstart[f*(NB+1)+b] = lower_bound(mch_f, ceil(b*IHS/NB)).
template <typename T>
__device__ __forceinline__ void bucket_body(const void* mch0v, const void* mch1v,
                                            int zch, int t) {
    int f = (t > NBUCKETS) ? 1 : 0;
    int b = t - f * (NBUCKETS + 1);
    const T* mch = (const T*)((f == 0) ? mch0v : mch1v);
    long long thr = (long long)(((unsigned long long)b * IHS + NBUCKETS - 1)
                                / NBUCKETS);
    g_bstart[t] = lower_bound_range<T>(mch, 0, zch, thr);
}

__global__ void bucket_kernel(const void* mch0, const void* mch1, int zch) {
    int t = blockIdx.x * blockDim.x + threadIdx.x;
    if (t >= 2 * (NBUCKETS + 1)) return;
    if (detect_is64(mch0)) bucket_body<long long>(mch0, mch1, zch, t);
    else                   bucket_body<int>(mch0, mch1, zch, t);
}

// ---------------------------------------------------------------------------
// Kernel A: one WARP per TWO embedding rows (emb_dim=128). Each lane issues
// two independent float4 loads (MLP=2), two shuffle reduces, lane 0 writes
// both sums. zch is even so a warp's row pair never straddles features.
__global__ void rowsum_kernel(const float* __restrict__ emb0,
                              const float* __restrict__ emb1, int zch) {
    const int warp = (blockIdx.x * blockDim.x + threadIdx.x) >> 5;
    const int lane = threadIdx.x & 31;
    const int slot0 = warp * 2;
    if (slot0 >= 2 * zch) return;
    const int slot1 = slot0 + 1;

    const int f0 = (slot0 >= zch) ? 1 : 0;
    const int f1 = (slot1 >= zch) ? 1 : 0;
    const int r0 = slot0 - f0 * zch;
    const int r1 = slot1 - f1 * zch;
    const float* __restrict__ e0 = (f0 == 0) ? emb0 : emb1;
    const float* __restrict__ e1 = (f1 == 0) ? emb0 : emb1;

    const float4 a = reinterpret_cast<const float4*>(e0 + (size_t)r0 * 128)[lane];
    const float4 b = reinterpret_cast<const float4*>(e1 + (size_t)r1 * 128)[lane];
    float s0 = (a.x + a.y) + (a.z + a.w);
    float s1 = (b.x + b.y) + (b.z + b.w);
    #pragma unroll
    for (int o = 16; o > 0; o >>= 1) {
        s0 += __shfl_down_sync(0xffffffffu, s0, o);
        s1 += __shfl_down_sync(0xffffffffu, s1, o);
    }
    if (lane == 0) {
        g_rowsum[f0 * ZCH_CAP + r0] = s0;
        g_rowsum[f1 * ZCH_CAP + r1] = s1;
    }
}

// ---------------------------------------------------------------------------
// Per-id body: bucketized lower_bound -> remapped index (float to d_out),
// gather 4B rowsum (L2-resident); returns it for the reduction.
template <typename T>
__device__ __forceinline__ float search_one(const void* ids0v, const void* ids1v,
                                            const void* mch0v, const void* mch1v,
                                            float* __restrict__ out,
                                            int n, int zch, int out_size,
                                            int tid) {
    const int f = (tid >= n) ? 1 : 0;
    const int i = tid - f * n;
    const T* __restrict__ ids = (const T*)((f == 0) ? ids0v : ids1v);
    const T* __restrict__ mch = (const T*)((f == 0) ? mch0v : mch1v);

    const long long id = (long long)ids[i];
    int b = (int)((unsigned long long)id * NBUCKETS / IHS);
    if (b < 0) b = 0;
    if (b > NBUCKETS - 1) b = NBUCKETS - 1;
    const int bi  = f * (NBUCKETS + 1) + b;
    const int lo0 = __ldg(&g_bstart[bi]);
    const int hi0 = __ldg(&g_bstart[bi + 1]);

    int pos = lower_bound_range<T>(mch, lo0, hi0 - lo0, id);
    if (pos > zch - 1) pos = zch - 1;
    const int r = ((long long)mch[pos] == id) ? pos : (zch - 1);

    if (1 + tid < out_size)
        out[1 + tid] = (float)r;          // remapped_0 then remapped_1
    return __ldg(&g_rowsum[f * ZCH_CAP + r]);
}

// ---------------------------------------------------------------------------
// Kernel B: TWO ids per thread (independent probe chains -> 2x MLP), block
// reduce, block partial; the last block to finish does the deterministic
// fixed-order double reduce and writes the loss (fused finalize).
__global__ void search_kernel(const void* ids0, const void* ids1,
                              const void* mch0, const void* mch1,
                              float* __restrict__ out,
                              int n, int zch, int out_size, int emb_dim) {
    const int base = blockIdx.x * (2 * blockDim.x) + threadIdx.x;
    const int j0 = base;
    const int j1 = base + blockDim.x;
    const int total = 2 * n;
    const int is64 = detect_is64(mch0);

    float s = 0.0f;
    if (is64) {                            // uniform branch
        if (j0 < total) s += search_one<long long>(ids0, ids1, mch0, mch1,
                                                   out, n, zch, out_size, j0);
        if (j1 < total) s += search_one<long long>(ids0, ids1, mch0, mch1,
                                                   out, n, zch, out_size, j1);
    } else {
        if (j0 < total) s += search_one<int>(ids0, ids1, mch0, mch1,
                                             out, n, zch, out_size, j0);
        if (j1 < total) s += search_one<int>(ids0, ids1, mch0, mch1,
                                             out, n, zch, out_size, j1);
    }

    // Warp shuffle reduce, then one cross-warp pass.
    #pragma unroll
    for (int o = 16; o > 0; o >>= 1)
        s += __shfl_down_sync(0xffffffffu, s, o);

    __shared__ float warp_sums[8];        // blockDim = 256 -> 8 warps
    __shared__ int   is_last;
    const int lane = threadIdx.x & 31;
    const int wid  = threadIdx.x >> 5;
    if (lane == 0) warp_sums[wid] = s;
    __syncthreads();
    if (threadIdx.x == 0) {
        float b2 = 0.0f;
        #pragma unroll
        for (int w = 0; w < 8; w++) b2 += warp_sums[w];
        g_partial[blockIdx.x] = b2;
        __threadfence();
        int t = atomicAdd(&g_ticket, 1);
        is_last = (t == (int)gridDim.x - 1) ? 1 : 0;
    }
    __syncthreads();

    // Fused finalize: last block does fixed-order double reduction.
    if (is_last) {
        __shared__ double red[256];
        double acc = 0.0;
        for (int i = threadIdx.x; i < (int)gridDim.x; i += 256)
            acc += (double)g_partial[i];
        red[threadIdx.x] = acc;
        __syncthreads();
        for (int o = 128; o > 0; o >>= 1) {
            if (threadIdx.x < (unsigned)o) red[threadIdx.x] += red[threadIdx.x + o];
            __syncthreads();
        }
        if (threadIdx.x == 0) {
            out[0] = (float)(red[0] / ((double)total * (double)emb_dim));
            g_ticket = 0;                 // reset for next graph replay
        }
    }
}

// ---------------------------------------------------------------------------
extern "C" void kernel_launch(void* const* d_in, const int* in_sizes, int n_in,
                              void* d_out, int out_size) {
    // Identify inputs by element count (robust to metadata ordering):
    //   ~51.2M -> emb, ~1M -> ids, ~400K -> mch. First hit = feature 0.
    const void* idsp[2] = {0, 0};
    const void* mchp[2] = {0, 0};
    const void* embp[2] = {0, 0};
    int n_ids = 0, n_mch = 0, n_emb = 0;
    int sz_ids = 0, sz_mch = 0, sz_emb = 0;
    for (int i = 0; i < n_in; i++) {
        int s = in_sizes[i];
        if (s > 10000000)      { if (n_emb < 2) { embp[n_emb++] = d_in[i]; sz_emb = s; } }
        else if (s > 600000)   { if (n_ids < 2) { idsp[n_ids++] = d_in[i]; sz_ids = s; } }
        else                   { if (n_mch < 2) { mchp[n_mch++] = d_in[i]; sz_mch = s; } }
    }
    float* out = (float*)d_out;

    const int n       = sz_ids;                    // ids per feature (1e6)
    int       zch     = sz_mch;                    // 400000
    if (zch > ZCH_CAP) zch = ZCH_CAP;
    const int emb_dim = (zch > 0) ? (sz_emb / zch) : 128;   // 128

    {   // Bucket index.
        const int total = 2 * (NBUCKETS + 1);
        bucket_kernel<<<(total + 255) / 256, 256>>>(mchp[0], mchp[1], zch);
    }

    // Kernel A: warp per 2 rows, 8 warps per 256-thread block.
    {
        const int warps = (2 * zch + 1) / 2;       // = zch
        rowsum_kernel<<<(warps + 7) / 8, 256>>>((const float*)embp[0],
                                                (const float*)embp[1], zch);
    }

    // Kernel B (+fused finalize): two ids per thread.
    const int nblocks = (2 * n + 511) / 512;
    search_kernel<<<nblocks, 256>>>(idsp[0], idsp[1], mchp[0], mchp[1],
                                    out, n, zch, out_size, emb_dim);
}

// round 14
// speedup vs baseline: 6.9974x; 1.2274x over previous
#include <cuda_runtime.h>
#include <cstdint>

#define ZCH_CAP 400000
#define NBUCKETS 65536
#define IHS 4000000ULL           // INPUT_HASH_SIZE
#define GGRID 2048               // gather grid (fixed, grid-strided)

// Scratch (no cudaMalloc allowed). Flat arrays, feature-offset indexed.
__device__ int    g_bstart[2 * (NBUCKETS + 1)];
__device__ int    g_count[2 * ZCH_CAP];
__device__ int    g_miss[2];
__device__ double g_partial_d[GGRID];
__device__ int    g_ticket;      // zero-init; reset by finalizing block

// ---------------------------------------------------------------------------
// Inline dtype probe: mch values < 2^22, so int64 storage => odd int32 words
// of the first entries are all zero (P[false positive with int32] ~ 1e-12).
__device__ __forceinline__ int detect_is64(const void* mch0) {
    const int* w = (const int*)mch0;
    int acc = 0;
    #pragma unroll
    for (int k = 1; k < 16; k += 2) acc |= w[k];
    return acc == 0;
}

__device__ __forceinline__ int bucket_of(long long v) {
    return (int)((unsigned long long)v * NBUCKETS / IHS);
}

// ---------------------------------------------------------------------------
// lower_bound (== jnp.searchsorted side='left') over a sorted range of T.
template <typename T>
__device__ __forceinline__ int lower_bound_range(const T* __restrict__ t,
                                                 int lo, int n, long long key) {
    #pragma unroll 1
    while (n > 0) {
        int half = n >> 1;
        long long v = (long long)t[lo + half];
        if (v < key) { lo += half + 1; n -= half + 1; }
        else         { n = half; }
    }
    return lo;
}

// ---------------------------------------------------------------------------
// Prep: streaming scatter bucket build + zero histogram/miss counters.
// start[b] = first j with B(v_j) >= b  (== lower_bound(mch, ceil(b*IHS/NB))).
// Thread j fills buckets (B(v_{j-1}), B(v_j)]; j==0 fills [0, B(v_0)];
// j==zch-1 also fills (B(v_last), NBUCKETS].
template <typename T>
__device__ __forceinline__ void prep_body(const void* mchv, int zch,
                                          int f, int j) {
    const T* __restrict__ m = (const T*)mchv;
    const int base = f * (NBUCKETS + 1);
    const long long vj = (long long)m[j];
    const int bhi = bucket_of(vj);
    if (j == 0) {
        for (int b = 0; b <= bhi; b++) g_bstart[base + b] = 0;
    } else {
        const int blo = bucket_of((long long)m[j - 1]);
        for (int b = blo + 1; b <= bhi; b++) g_bstart[base + b] = j;
    }
    if (j == zch - 1) {
        for (int b = bhi + 1; b <= NBUCKETS; b++) g_bstart[base + b] = zch;
    }
}

__global__ void prep_kernel(const void* mch0, const void* mch1, int zch) {
    const int t = blockIdx.x * blockDim.x + threadIdx.x;
    if (t >= 2 * zch) return;
    const int f = (t >= zch) ? 1 : 0;
    const int j = t - f * zch;
    g_count[f * ZCH_CAP + j] = 0;          // zero histogram for this replay
    if (t == 0) { g_miss[0] = 0; g_miss[1] = 0; }
    const void* mch = (f == 0) ? mch0 : mch1;
    if (detect_is64(mch0)) prep_body<long long>(mch, zch, f, j);
    else                   prep_body<int>(mch, zch, f, j);
}

// ---------------------------------------------------------------------------
// Per-id: bucketized lower_bound -> remapped index (float to d_out); on hit
// fire-and-forget count atomic; returns 1 if miss (caller counts per feature).
template <typename T>
__device__ __forceinline__ int search_one(const void* ids0v, const void* ids1v,
                                          const void* mch0v, const void* mch1v,
                                          float* __restrict__ out,
                                          int n, int zch, int out_size,
                                          int tid, int f) {
    const int i = tid - f * n;
    const T* __restrict__ ids = (const T*)((f == 0) ? ids0v : ids1v);
    const T* __restrict__ mch = (const T*)((f == 0) ? mch0v : mch1v);

    const long long id = (long long)ids[i];
    int b = bucket_of(id);
    if (b < 0) b = 0;
    if (b > NBUCKETS - 1) b = NBUCKETS - 1;
    const int bi  = f * (NBUCKETS + 1) + b;
    const int lo0 = __ldg(&g_bstart[bi]);
    const int hi0 = __ldg(&g_bstart[bi + 1]);

    int pos = lower_bound_range<T>(mch, lo0, hi0 - lo0, id);
    if (pos > zch - 1) pos = zch - 1;
    const int hit = ((long long)mch[pos] == id) ? 1 : 0;
    const int r   = hit ? pos : (zch - 1);

    if (1 + tid < out_size)
        out[1 + tid] = (float)r;           // remapped_0 then remapped_1
    if (hit) atomicAdd(&g_count[f * ZCH_CAP + pos], 1);
    return 1 - hit;
}

// ---------------------------------------------------------------------------
// Search: two ids per thread (2x MLP). Misses block-reduced (packed 16+16)
// and added with 2 int atomics per block. All accumulation is integer =>
// deterministic across replays.
__global__ void search_kernel(const void* ids0, const void* ids1,
                              const void* mch0, const void* mch1,
                              float* __restrict__ out,
                              int n, int zch, int out_size) {
    const int base = blockIdx.x * (2 * blockDim.x) + threadIdx.x;
    const int j0 = base;
    const int j1 = base + blockDim.x;
    const int total = 2 * n;
    const int is64 = detect_is64(mch0);

    int m0 = 0, m1 = 0;                    // per-thread miss counts
    if (is64) {                            // uniform branch
        if (j0 < total) {
            int f = (j0 >= n); int miss = search_one<long long>(
                ids0, ids1, mch0, mch1, out, n, zch, out_size, j0, f);
            if (f) m1 += miss; else m0 += miss;
        }
        if (j1 < total) {
            int f = (j1 >= n); int miss = search_one<long long>(
                ids0, ids1, mch0, mch1, out, n, zch, out_size, j1, f);
            if (f) m1 += miss; else m0 += miss;
        }
    } else {
        if (j0 < total) {
            int f = (j0 >= n); int miss = search_one<int>(
                ids0, ids1, mch0, mch1, out, n, zch, out_size, j0, f);
            if (f) m1 += miss; else m0 += miss;
        }
        if (j1 < total) {
            int f = (j1 >= n); int miss = search_one<int>(
                ids0, ids1, mch0, mch1, out, n, zch, out_size, j1, f);
            if (f) m1 += miss; else m0 += miss;
        }
    }

    int packed = m0 | (m1 << 16);          // <=512 ids/block: fits 16 bits
    #pragma unroll
    for (int o = 16; o > 0; o >>= 1)
        packed += __shfl_down_sync(0xffffffffu, packed, o);

    __shared__ int warp_m[8];
    const int lane = threadIdx.x & 31;
    const int wid  = threadIdx.x >> 5;
    if (lane == 0) warp_m[wid] = packed;
    __syncthreads();
    if (threadIdx.x == 0) {
        int p = 0;
        #pragma unroll
        for (int w = 0; w < 8; w++) p += warp_m[w];
        if (p & 0xffff)  atomicAdd(&g_miss[0], p & 0xffff);
        if (p >> 16)     atomicAdd(&g_miss[1], p >> 16);
    }
}

// ---------------------------------------------------------------------------
// Gather: grid-strided warp-per-slot. Only slots with weight>0 load their
// 512B row (~22% of slots). weight = count[slot] (+ miss_f at slot zch-1).
// Double accumulation in fixed slot order per warp; fixed-order block and
// final reductions; last block (ticket) writes the loss. Deterministic.
__global__ void gather_kernel(const float* __restrict__ emb0,
                              const float* __restrict__ emb1,
                              float* __restrict__ out,
                              int zch, int n, int emb_dim) {
    const int lane  = threadIdx.x & 31;
    const int wid   = threadIdx.x >> 5;
    const int gwarp = blockIdx.x * 8 + wid;
    const int nwarps = GGRID * 8;
    const int nslots = 2 * zch;

    double acc = 0.0;
    #pragma unroll 1
    for (int slot = gwarp; slot < nslots; slot += nwarps) {
        const int f = (slot >= zch) ? 1 : 0;
        const int r = slot - f * zch;
        int w = __ldg(&g_count[f * ZCH_CAP + r]);
        if (r == zch - 1) w += g_miss[f];
        if (w == 0) continue;
        const float* __restrict__ e = (f == 0) ? emb0 : emb1;
        const float4 v = reinterpret_cast<const float4*>(
            e + (size_t)r * 128)[lane];
        float s = (v.x + v.y) + (v.z + v.w);
        #pragma unroll
        for (int o = 16; o > 0; o >>= 1)
            s += __shfl_down_sync(0xffffffffu, s, o);
        if (lane == 0) acc += (double)s * (double)w;
    }

    __shared__ double wacc[8];
    __shared__ int is_last;
    if (lane == 0) wacc[wid] = acc;
    __syncthreads();
    if (threadIdx.x == 0) {
        double b = 0.0;
        #pragma unroll
        for (int w = 0; w < 8; w++) b += wacc[w];
        g_partial_d[blockIdx.x] = b;
        __threadfence();
        int t = atomicAdd(&g_ticket, 1);
        is_last = (t == GGRID - 1) ? 1 : 0;
    }
    __syncthreads();

    if (is_last) {
        __shared__ double red[256];
        double a2 = 0.0;
        for (int i = threadIdx.x; i < GGRID; i += 256)
            a2 += g_partial_d[i];
        red[threadIdx.x] = a2;
        __syncthreads();
        for (int o = 128; o > 0; o >>= 1) {
            if (threadIdx.x < (unsigned)o) red[threadIdx.x] += red[threadIdx.x + o];
            __syncthreads();
        }
        if (threadIdx.x == 0) {
            out[0] = (float)(red[0] / ((double)(2 * n) * (double)emb_dim));
            g_ticket = 0;                  // reset for next graph replay
        }
    }
}

// ---------------------------------------------------------------------------
extern "C" void kernel_launch(void* const* d_in, const int* in_sizes, int n_in,
                              void* d_out, int out_size) {
    // Identify inputs by element count (robust to metadata ordering):
    //   ~51.2M -> emb, ~1M -> ids, ~400K -> mch. First hit = feature 0.
    const void* idsp[2] = {0, 0};
    const void* mchp[2] = {0, 0};
    const void* embp[2] = {0, 0};
    int n_ids = 0, n_mch = 0, n_emb = 0;
    int sz_ids = 0, sz_mch = 0, sz_emb = 0;
    for (int i = 0; i < n_in; i++) {
        int s = in_sizes[i];
        if (s > 10000000)      { if (n_emb < 2) { embp[n_emb++] = d_in[i]; sz_emb = s; } }
        else if (s > 600000)   { if (n_ids < 2) { idsp[n_ids++] = d_in[i]; sz_ids = s; } }
        else                   { if (n_mch < 2) { mchp[n_mch++] = d_in[i]; sz_mch = s; } }
    }
    float* out = (float*)d_out;

    const int n       = sz_ids;                    // ids per feature (1e6)
    int       zch     = sz_mch;                    // 400000
    if (zch > ZCH_CAP) zch = ZCH_CAP;
    const int emb_dim = (zch > 0) ? (sz_emb / zch) : 128;   // 128

    // 1) Bucket scatter + zero counters.
    prep_kernel<<<(2 * zch + 255) / 256, 256>>>(mchp[0], mchp[1], zch);

    // 2) Search + histogram: two ids per thread.
    const int nblocks = (2 * n + 511) / 512;
    search_kernel<<<nblocks, 256>>>(idsp[0], idsp[1], mchp[0], mchp[1],
                                    out, n, zch, out_size);

    // 3) Weighted selective rowsum gather + fused finalize.
    gather_kernel<<<GGRID, 256>>>((const float*)embp[0], (const float*)embp[1],
                                  out, zch, n, emb_dim);
}

// round 16
// speedup vs baseline: 7.2571x; 1.0371x over previous
#include <cuda_runtime.h>
#include <cstdint>

#define ZCH_CAP 400000
#define NBUCKETS 65536
#define IHS 4000000ULL           // INPUT_HASH_SIZE
#define GCHUNK 512               // slots per gather block
#define MAX_GBLOCKS 4096         // >= ceil(2*ZCH_CAP/GCHUNK) = 1563

// Scratch (no cudaMalloc allowed). Flat arrays, feature-offset indexed.
__device__ int    g_bstart[2 * (NBUCKETS + 1)];
__device__ int    g_count[2 * ZCH_CAP];
__device__ int    g_miss[2];
__device__ double g_partial_d[MAX_GBLOCKS];
__device__ int    g_ticket;      // zero-init; reset by finalizing block

// ---------------------------------------------------------------------------
// Inline dtype probe: mch values < 2^22, so int64 storage => odd int32 words
// of the first entries are all zero (P[false positive with int32] ~ 1e-12).
__device__ __forceinline__ int detect_is64(const void* mch0) {
    const int* w = (const int*)mch0;
    int acc = 0;
    #pragma unroll
    for (int k = 1; k < 16; k += 2) acc |= w[k];
    return acc == 0;
}

__device__ __forceinline__ int bucket_of(long long v) {
    return (int)((unsigned long long)v * NBUCKETS / IHS);
}

// ---------------------------------------------------------------------------
// lower_bound (== jnp.searchsorted side='left') over a sorted range of T.
template <typename T>
__device__ __forceinline__ int lower_bound_range(const T* __restrict__ t,
                                                 int lo, int n, long long key) {
    #pragma unroll 1
    while (n > 0) {
        int half = n >> 1;
        long long v = (long long)t[lo + half];
        if (v < key) { lo += half + 1; n -= half + 1; }
        else         { n = half; }
    }
    return lo;
}

// ---------------------------------------------------------------------------
// Prep: streaming scatter bucket build + zero histogram/miss counters.
// start[b] = first j with B(v_j) >= b  (== lower_bound(mch, ceil(b*IHS/NB))).
template <typename T>
__device__ __forceinline__ void prep_body(const void* mchv, int zch,
                                          int f, int j) {
    const T* __restrict__ m = (const T*)mchv;
    const int base = f * (NBUCKETS + 1);
    const long long vj = (long long)m[j];
    const int bhi = bucket_of(vj);
    if (j == 0) {
        for (int b = 0; b <= bhi; b++) g_bstart[base + b] = 0;
    } else {
        const int blo = bucket_of((long long)m[j - 1]);
        for (int b = blo + 1; b <= bhi; b++) g_bstart[base + b] = j;
    }
    if (j == zch - 1) {
        for (int b = bhi + 1; b <= NBUCKETS; b++) g_bstart[base + b] = zch;
    }
}

__global__ void prep_kernel(const void* mch0, const void* mch1, int zch) {
    const int t = blockIdx.x * blockDim.x + threadIdx.x;
    if (t >= 2 * zch) return;
    const int f = (t >= zch) ? 1 : 0;
    const int j = t - f * zch;
    g_count[f * ZCH_CAP + j] = 0;          // zero histogram for this replay
    if (t == 0) { g_miss[0] = 0; g_miss[1] = 0; }
    const void* mch = (f == 0) ? mch0 : mch1;
    if (detect_is64(mch0)) prep_body<long long>(mch, zch, f, j);
    else                   prep_body<int>(mch, zch, f, j);
}

// ---------------------------------------------------------------------------
// Per-id: bucketized lower_bound -> remapped index (float to d_out); on hit
// fire-and-forget count atomic; returns 1 if miss.
template <typename T>
__device__ __forceinline__ int search_one(const void* ids0v, const void* ids1v,
                                          const void* mch0v, const void* mch1v,
                                          float* __restrict__ out,
                                          int n, int zch, int out_size,
                                          int tid, int f) {
    const int i = tid - f * n;
    const T* __restrict__ ids = (const T*)((f == 0) ? ids0v : ids1v);
    const T* __restrict__ mch = (const T*)((f == 0) ? mch0v : mch1v);

    const long long id = (long long)ids[i];
    int b = bucket_of(id);
    if (b < 0) b = 0;
    if (b > NBUCKETS - 1) b = NBUCKETS - 1;
    const int bi  = f * (NBUCKETS + 1) + b;
    const int lo0 = __ldg(&g_bstart[bi]);
    const int hi0 = __ldg(&g_bstart[bi + 1]);

    int pos = lower_bound_range<T>(mch, lo0, hi0 - lo0, id);
    if (pos > zch - 1) pos = zch - 1;
    const int hit = ((long long)mch[pos] == id) ? 1 : 0;
    const int r   = hit ? pos : (zch - 1);

    if (1 + tid < out_size)
        out[1 + tid] = (float)r;           // remapped_0 then remapped_1
    if (hit) atomicAdd(&g_count[f * ZCH_CAP + pos], 1);
    return 1 - hit;
}

// ---------------------------------------------------------------------------
// Search: two ids per thread (2x MLP). Misses block-reduced (packed 16+16),
// 2 int atomics per block. Integer accumulation => deterministic.
__global__ void search_kernel(const void* ids0, const void* ids1,
                              const void* mch0, const void* mch1,
                              float* __restrict__ out,
                              int n, int zch, int out_size) {
    const int base = blockIdx.x * (2 * blockDim.x) + threadIdx.x;
    const int j0 = base;
    const int j1 = base + blockDim.x;
    const int total = 2 * n;
    const int is64 = detect_is64(mch0);

    int m0 = 0, m1 = 0;
    if (is64) {                            // uniform branch
        if (j0 < total) {
            int f = (j0 >= n); int miss = search_one<long long>(
                ids0, ids1, mch0, mch1, out, n, zch, out_size, j0, f);
            if (f) m1 += miss; else m0 += miss;
        }
        if (j1 < total) {
            int f = (j1 >= n); int miss = search_one<long long>(
                ids0, ids1, mch0, mch1, out, n, zch, out_size, j1, f);
            if (f) m1 += miss; else m0 += miss;
        }
    } else {
        if (j0 < total) {
            int f = (j0 >= n); int miss = search_one<int>(
                ids0, ids1, mch0, mch1, out, n, zch, out_size, j0, f);
            if (f) m1 += miss; else m0 += miss;
        }
        if (j1 < total) {
            int f = (j1 >= n); int miss = search_one<int>(
                ids0, ids1, mch0, mch1, out, n, zch, out_size, j1, f);
            if (f) m1 += miss; else m0 += miss;
        }
    }

    int packed = m0 | (m1 << 16);
    #pragma unroll
    for (int o = 16; o > 0; o >>= 1)
        packed += __shfl_down_sync(0xffffffffu, packed, o);

    __shared__ int warp_m[8];
    const int lane = threadIdx.x & 31;
    const int wid  = threadIdx.x >> 5;
    if (lane == 0) warp_m[wid] = packed;
    __syncthreads();
    if (threadIdx.x == 0) {
        int p = 0;
        #pragma unroll
        for (int w = 0; w < 8; w++) p += warp_m[w];
        if (p & 0xffff)  atomicAdd(&g_miss[0], p & 0xffff);
        if (p >> 16)     atomicAdd(&g_miss[1], p >> 16);
    }
}

// ---------------------------------------------------------------------------
// Gather: each block owns GCHUNK contiguous slots. Coalesced count scan ->
// deterministic ballot/popc compaction into a shared (slot, weight) list ->
// 8 warps process the list with a 2-deep pipeline (two rows in flight).
// Fixed-order double accumulation everywhere; ticketed fused finalize.
__global__ void gather_kernel(const float* __restrict__ emb0,
                              const float* __restrict__ emb1,
                              float* __restrict__ out,
                              int zch, int n, int emb_dim) {
    __shared__ int   slist[GCHUNK];
    __shared__ int   wlist[GCHUNK];
    __shared__ int   warp_tot[8];
    __shared__ int   s_cnt;
    __shared__ double wacc[8];
    __shared__ int   is_last;

    const int lane = threadIdx.x & 31;
    const int wid  = threadIdx.x >> 5;
    const int nslots = 2 * zch;
    const int chunk0 = blockIdx.x * GCHUNK;

    if (threadIdx.x == 0) s_cnt = 0;
    __syncthreads();

    // Two compaction rounds (positions t and t+256), each slot-ordered and
    // deterministic: ballot -> lane offset by popc, warp totals scanned in
    // fixed order.
    int base_idx = 0;
    #pragma unroll
    for (int round = 0; round < 2; round++) {
        const int slot = chunk0 + round * 256 + threadIdx.x;
        int w = 0;
        if (slot < nslots) {
            const int f = (slot >= zch) ? 1 : 0;
            const int r = slot - f * zch;
            w = g_count[f * ZCH_CAP + r];
            if (r == zch - 1) w += g_miss[f];
        }
        const unsigned mask = __ballot_sync(0xffffffffu, w > 0);
        const int lane_off = __popc(mask & ((1u << lane) - 1u));
        if (lane == 0) warp_tot[wid] = __popc(mask);
        __syncthreads();
        int woff = 0;
        #pragma unroll
        for (int k = 0; k < 8; k++) woff += (k < wid) ? warp_tot[k] : 0;
        if (w > 0) {
            const int idx = base_idx + woff + lane_off;
            slist[idx] = slot;
            wlist[idx] = w;
        }
        int round_tot = 0;
        #pragma unroll
        for (int k = 0; k < 8; k++) round_tot += warp_tot[k];
        base_idx += round_tot;
        __syncthreads();
    }
    if (threadIdx.x == 0) s_cnt = base_idx;
    __syncthreads();
    const int cnt = s_cnt;

    // Process list: warp takes entries wid, wid+8, ... with 2 in flight.
    double acc = 0.0;
    for (int k = wid; k < cnt; k += 16) {
        const int k2 = k + 8;
        const int slot1 = slist[k];
        const int f1 = (slot1 >= zch) ? 1 : 0;
        const int r1 = slot1 - f1 * zch;
        const float* __restrict__ e1 = (f1 == 0) ? emb0 : emb1;
        const float4 a = reinterpret_cast<const float4*>(
            e1 + (size_t)r1 * 128)[lane];

        float4 b = make_float4(0.f, 0.f, 0.f, 0.f);
        int w2 = 0;
        if (k2 < cnt) {
            const int slot2 = slist[k2];
            const int f2 = (slot2 >= zch) ? 1 : 0;
            const int r2 = slot2 - f2 * zch;
            const float* __restrict__ e2 = (f2 == 0) ? emb0 : emb1;
            b = reinterpret_cast<const float4*>(e2 + (size_t)r2 * 128)[lane];
            w2 = wlist[k2];
        }

        float s1 = (a.x + a.y) + (a.z + a.w);
        float s2 = (b.x + b.y) + (b.z + b.w);
        #pragma unroll
        for (int o = 16; o > 0; o >>= 1) {
            s1 += __shfl_down_sync(0xffffffffu, s1, o);
            s2 += __shfl_down_sync(0xffffffffu, s2, o);
        }
        if (lane == 0) {
            acc += (double)s1 * (double)wlist[k];
            if (k2 < cnt) acc += (double)s2 * (double)w2;
        }
    }

    if (lane == 0) wacc[wid] = acc;
    __syncthreads();
    if (threadIdx.x == 0) {
        double bsum = 0.0;
        #pragma unroll
        for (int w = 0; w < 8; w++) bsum += wacc[w];
        g_partial_d[blockIdx.x] = bsum;
        __threadfence();
        int t = atomicAdd(&g_ticket, 1);
        is_last = (t == (int)gridDim.x - 1) ? 1 : 0;
    }
    __syncthreads();

    if (is_last) {
        __shared__ double red[256];
        double a2 = 0.0;
        for (int i = threadIdx.x; i < (int)gridDim.x; i += 256)
            a2 += g_partial_d[i];
        red[threadIdx.x] = a2;
        __syncthreads();
        for (int o = 128; o > 0; o >>= 1) {
            if (threadIdx.x < (unsigned)o) red[threadIdx.x] += red[threadIdx.x + o];
            __syncthreads();
        }
        if (threadIdx.x == 0) {
            out[0] = (float)(red[0] / ((double)(2 * n) * (double)emb_dim));
            g_ticket = 0;                  // reset for next graph replay
        }
    }
}

// ---------------------------------------------------------------------------
extern "C" void kernel_launch(void* const* d_in, const int* in_sizes, int n_in,
                              void* d_out, int out_size) {
    // Identify inputs by element count (robust to metadata ordering).
    const void* idsp[2] = {0, 0};
    const void* mchp[2] = {0, 0};
    const void* embp[2] = {0, 0};
    int n_ids = 0, n_mch = 0, n_emb = 0;
    int sz_ids = 0, sz_mch = 0, sz_emb = 0;
    for (int i = 0; i < n_in; i++) {
        int s = in_sizes[i];
        if (s > 10000000)      { if (n_emb < 2) { embp[n_emb++] = d_in[i]; sz_emb = s; } }
        else if (s > 600000)   { if (n_ids < 2) { idsp[n_ids++] = d_in[i]; sz_ids = s; } }
        else                   { if (n_mch < 2) { mchp[n_mch++] = d_in[i]; sz_mch = s; } }
    }
    float* out = (float*)d_out;

    const int n       = sz_ids;                    // ids per feature (1e6)
    int       zch     = sz_mch;                    // 400000
    if (zch > ZCH_CAP) zch = ZCH_CAP;
    const int emb_dim = (zch > 0) ? (sz_emb / zch) : 128;   // 128

    // 1) Bucket scatter + zero counters.
    prep_kernel<<<(2 * zch + 255) / 256, 256>>>(mchp[0], mchp[1], zch);

    // 2) Search + histogram: two ids per thread.
    const int nblocks = (2 * n + 511) / 512;
    search_kernel<<<nblocks, 256>>>(idsp[0], idsp[1], mchp[0], mchp[1],
                                    out, n, zch, out_size);

    // 3) Compacted weighted rowsum gather + fused finalize.
    int gblocks = (2 * zch + GCHUNK - 1) / GCHUNK;
    if (gblocks > MAX_GBLOCKS) gblocks = MAX_GBLOCKS;   // zch<=ZCH_CAP holds
    gather_kernel<<<gblocks, 256>>>((const float*)embp[0],
                                    (const float*)embp[1],
                                    out, zch, n, emb_dim);
}